// round 10
// baseline (speedup 1.0000x reference)
#include <cuda_runtime.h>
#include <cstdint>
#include <math.h>

// ---------------------------------------------------------------------------
// Problem constants
// ---------------------------------------------------------------------------
#define Bq   32
#define Sq   512
#define Eq   512
#define Tq   24
#define Hq   2
#define HDq  256
#define Mq   (Bq*Sq)      // 16384

// ---------------------------------------------------------------------------
// Scratch (paired arrays hold {hi,lo,hi+4,lo+4} float4s: 2*K floats per row)
// ---------------------------------------------------------------------------
__device__ float g_qkv   [Mq * 3 * Eq];            // plain QKV
__device__ float g_scores[Bq * Hq * Sq * Sq];      // raw scores
__device__ float g_attn  [Mq * Eq];                // plain attn out
__device__ float g_dec   [Mq * Eq];
__device__ float g_em    [Mq * Tq];
__device__ float g_encp  [Mq * 2 * Eq];            // enc paired
__device__ float g_winp  [3 * Eq * 2 * Eq];        // Win paired
__device__ float g_woutp [Eq * 2 * Eq];            // Wout paired
__device__ float g_qp    [Bq * Hq * Sq * 2 * HDq]; // Q paired per bh
__device__ float g_kp    [Bq * Hq * Sq * 2 * HDq]; // K paired per bh
__device__ float g_pp    [Bq * Hq * Sq * 2 * Sq];  // softmax probs paired
__device__ float g_vtp   [Bq * Hq * HDq * 2 * Sq]; // V^T paired
__device__ float g_attnp [Mq * 2 * Eq];            // attn paired
__device__ float g_wpad  [32 * Eq];
__device__ float g_bpad  [32];
__device__ float g_num   [Bq];
__device__ float g_den   [Bq];

// ---------------------------------------------------------------------------
// Helpers
// ---------------------------------------------------------------------------
__device__ __forceinline__ void tf32_split(float x, float& h, float& l) {
    asm("cvt.rna.tf32.f32 %0, %1;" : "=f"(h) : "f"(x));
    float d = x - h;
    asm("cvt.rna.tf32.f32 %0, %1;" : "=f"(l) : "f"(d));
}

__device__ __forceinline__ uint32_t smem_u32(const void* p) {
    uint32_t a;
    asm("{ .reg .u64 t; cvta.to.shared.u64 t, %1; cvt.u32.u64 %0, t; }" : "=r"(a) : "l"(p));
    return a;
}

__device__ __forceinline__ void cpa16(uint32_t s, const void* g) {
    asm volatile("cp.async.cg.shared.global [%0], [%1], 16;" :: "r"(s), "l"(g));
}

#define MMA_TF32(c, a0, a1, a2, a3, b0, b1) \
    asm volatile("mma.sync.aligned.m16n8k8.row.col.f32.tf32.tf32.f32 " \
        "{%0,%1,%2,%3}, {%4,%5,%6,%7}, {%8,%9}, {%0,%1,%2,%3};" \
        : "+f"((c)[0]), "+f"((c)[1]), "+f"((c)[2]), "+f"((c)[3]) \
        : "r"(__float_as_uint(a0)), "r"(__float_as_uint(a1)), \
          "r"(__float_as_uint(a2)), "r"(__float_as_uint(a3)), \
          "r"(__float_as_uint(b0)), "r"(__float_as_uint(b1)))

// ---------------------------------------------------------------------------
// 3xTF32 NT GEMM on pre-split paired operands, cp.async double-buffered.
// BM=BN=128, BK=16 (32 paired floats per row per tile), 256 threads
// (8 warps, 2x4 grid, 64x32 per warp). smem row stride 48 floats:
// LDS.128 fragment phases hit banks {16*gq+4*gr} = all 32, conflict-free.
// ---------------------------------------------------------------------------
#define BM 128
#define BN 128
#define SSTRIDE 48
#define ATILE (BM * SSTRIDE)              // 6144 floats
#define BTILE (BN * SSTRIDE)              // 6144 floats
#define STAGEF (ATILE + BTILE)            // 12288 floats
#define GEMM_SMEM (2 * STAGEF * 4)        // 98304 bytes (Cst 128*132=67584B fits)

__global__ __launch_bounds__(256, 2) void gemm_ps(
    const float* __restrict__ Ap, long long sAb, long long sAh,
    const float* __restrict__ Bp, long long sBb, long long sBh,
    const float* __restrict__ bias,
    float* __restrict__ C, int ldc, long long sCb, long long sCh,
    int K, float alpha, int relu, int H)
{
    extern __shared__ float smem[];
    uint32_t sb0 = smem_u32(smem);
    int tid = threadIdx.x, wid = tid >> 5, lane = tid & 31;
    int wm = wid & 1, wn = wid >> 1;          // 2 x 4 warp grid
    int gq = lane >> 2, gr = lane & 3;
    int z = blockIdx.z, zb = z / H, zh = z - zb * H;
    Ap += zb * sAb + zh * sAh;
    Bp += zb * sBb + zh * sBh;
    C  += zb * sCb + zh * sCh;
    int bm = blockIdx.y * BM, bn = blockIdx.x * BN;
    int twoK = K << 1;

    int crow = tid >> 3;                 // 0..31
    int cc   = tid & 7;                  // 16B chunk within 128B row slice
    const float* gA = Ap + (long long)(bm + crow) * twoK + cc * 4;
    const float* gB = Bp + (long long)(bn + crow) * twoK + cc * 4;
    uint32_t sA = sb0 + (uint32_t)(crow * SSTRIDE + cc * 4) * 4u;
    uint32_t sB = sb0 + (uint32_t)(ATILE + crow * SSTRIDE + cc * 4) * 4u;

    float acc[4][4][4];
    #pragma unroll
    for (int mi = 0; mi < 4; mi++)
        #pragma unroll
        for (int ni = 0; ni < 4; ni++)
            #pragma unroll
            for (int q = 0; q < 4; q++) acc[mi][ni][q] = 0.f;

    int nK = K >> 4;

    // prologue: tile 0 -> stage 0  (A: 4x32 rows, B: 4x32 rows)
    #pragma unroll
    for (int i = 0; i < 4; i++)
        cpa16(sA + i * (32 * SSTRIDE * 4), gA + (long long)i * 32 * twoK);
    #pragma unroll
    for (int i = 0; i < 4; i++)
        cpa16(sB + i * (32 * SSTRIDE * 4), gB + (long long)i * 32 * twoK);
    asm volatile("cp.async.commit_group;");

    for (int kt = 0; kt < nK; kt++) {
        int cur = kt & 1;
        if (kt + 1 < nK) {
            uint32_t soff = (uint32_t)((kt + 1) & 1) * (STAGEF * 4);
            const float* ga = gA + (kt + 1) * 32;
            const float* gb = gB + (kt + 1) * 32;
            #pragma unroll
            for (int i = 0; i < 4; i++)
                cpa16(sA + soff + i * (32 * SSTRIDE * 4), ga + (long long)i * 32 * twoK);
            #pragma unroll
            for (int i = 0; i < 4; i++)
                cpa16(sB + soff + i * (32 * SSTRIDE * 4), gb + (long long)i * 32 * twoK);
            asm volatile("cp.async.commit_group;");
            asm volatile("cp.async.wait_group 1;");
        } else {
            asm volatile("cp.async.wait_group 0;");
        }
        __syncthreads();

        const float* As = smem + cur * STAGEF;
        const float* Bs = As + ATILE;
        #pragma unroll
        for (int ks = 0; ks < 2; ks++) {
            int off = ks * 16 + gr * 4;
            float4 pb[4];
            #pragma unroll
            for (int ni = 0; ni < 4; ni++)
                pb[ni] = *(const float4*)&Bs[(wn * 32 + ni * 8 + gq) * SSTRIDE + off];
            #pragma unroll
            for (int mi = 0; mi < 4; mi++) {
                int ra = (wm * 64 + mi * 16 + gq) * SSTRIDE + off;
                float4 pa0 = *(const float4*)&As[ra];
                float4 pa1 = *(const float4*)&As[ra + 8 * SSTRIDE];
                #pragma unroll
                for (int ni = 0; ni < 4; ni++)
                    MMA_TF32(acc[mi][ni], pa0.x, pa1.x, pa0.z, pa1.z, pb[ni].x, pb[ni].z);
                #pragma unroll
                for (int ni = 0; ni < 4; ni++)
                    MMA_TF32(acc[mi][ni], pa0.x, pa1.x, pa0.z, pa1.z, pb[ni].y, pb[ni].w);
                #pragma unroll
                for (int ni = 0; ni < 4; ni++)
                    MMA_TF32(acc[mi][ni], pa0.y, pa1.y, pa0.w, pa1.w, pb[ni].x, pb[ni].z);
            }
        }
        __syncthreads();
    }

    // Epilogue: accs -> smem -> coalesced gmem
    float* Cst = smem;
    #pragma unroll
    for (int mi = 0; mi < 4; mi++) {
        int row = wm * 64 + mi * 16 + gq;
        #pragma unroll
        for (int ni = 0; ni < 4; ni++) {
            int col = wn * 32 + ni * 8 + gr * 2;
            Cst[row * 132 + col]           = acc[mi][ni][0];
            Cst[row * 132 + col + 1]       = acc[mi][ni][1];
            Cst[(row + 8) * 132 + col]     = acc[mi][ni][2];
            Cst[(row + 8) * 132 + col + 1] = acc[mi][ni][3];
        }
    }
    __syncthreads();

    for (int idx = tid; idx < BM * BN / 4; idx += 256) {
        int r2 = idx >> 5, c4 = (idx & 31) << 2;
        float4 v = *(float4*)&Cst[r2 * 132 + c4];
        v.x *= alpha; v.y *= alpha; v.z *= alpha; v.w *= alpha;
        if (bias) {
            float4 bb = *(const float4*)&bias[bn + c4];
            v.x += bb.x; v.y += bb.y; v.z += bb.z; v.w += bb.w;
        }
        if (relu) {
            v.x = fmaxf(v.x, 0.f); v.y = fmaxf(v.y, 0.f);
            v.z = fmaxf(v.z, 0.f); v.w = fmaxf(v.w, 0.f);
        }
        *(float4*)&C[(long long)(bm + r2) * ldc + bn + c4] = v;
    }
    __syncthreads();
}

// ---------------------------------------------------------------------------
// pack_dense: split a dense [R][512] fp32 matrix into paired layout [R][1024]
// ---------------------------------------------------------------------------
__global__ void pack_dense(const float* __restrict__ src, float* __restrict__ dst,
                           int total)
{
    int idx = blockIdx.x * blockDim.x + threadIdx.x;   // total = R*256
    if (idx >= total) return;
    int j = idx & 3, g = (idx >> 2) & 63, r = idx >> 8;
    int k = g * 8 + j;
    const float* sp = src + (long long)r * 512;
    float h0, l0, h1, l1;
    tf32_split(sp[k],     h0, l0);
    tf32_split(sp[k + 4], h1, l1);
    *(float4*)&dst[(long long)r * 1024 + g * 16 + j * 4] = make_float4(h0, l0, h1, l1);
}

// ---------------------------------------------------------------------------
// pack_qk: Q,K head-views of qkv -> paired dense per (b,h)
// ---------------------------------------------------------------------------
__global__ void pack_qk(const float* __restrict__ qkv,
                        float* __restrict__ Qp, float* __restrict__ Kp)
{
    int idx = blockIdx.x * blockDim.x + threadIdx.x;   // 4194304 total
    int j = idx & 3, g = (idx >> 2) & 31, s = (idx >> 7) & 511, bh = idx >> 16;
    int b = bh >> 1, h = bh & 1;
    const float* src = qkv + ((long long)(b * 512 + s)) * 1536 + h * 256;
    int k = g * 8 + j;
    long long o = ((long long)bh * 512 + s) * 512 + g * 16 + j * 4;
    float h0, l0, h1, l1;
    tf32_split(src[k],       h0, l0);
    tf32_split(src[k + 4],   h1, l1);
    *(float4*)&Qp[o] = make_float4(h0, l0, h1, l1);
    tf32_split(src[512 + k],     h0, l0);
    tf32_split(src[512 + k + 4], h1, l1);
    *(float4*)&Kp[o] = make_float4(h0, l0, h1, l1);
}

// ---------------------------------------------------------------------------
// V transpose -> paired: vtp[bh][n][pair(k)]  (K = 512 keys)
// ---------------------------------------------------------------------------
__global__ void transpose_vp(const float* __restrict__ qkv, float* __restrict__ vtp)
{
    __shared__ float t[32][33];
    int z = blockIdx.z, zb = z >> 1, zh = z & 1;
    const float* src = qkv + (long long)zb * Sq * 3 * Eq + 2 * Eq + zh * HDq;
    float* dst = vtp + (long long)z * HDq * 1024;
    int k0 = blockIdx.x * 32, n0 = blockIdx.y * 32;
    int tx = threadIdx.x, ty = threadIdx.y;
    #pragma unroll
    for (int j = 0; j < 4; j++)
        t[ty + j * 8][tx] = src[(long long)(k0 + ty + j * 8) * (3 * Eq) + n0 + tx];
    __syncthreads();
    #pragma unroll
    for (int j = 0; j < 4; j++) {
        float val = t[tx][ty + j * 8];
        float hi, lo;
        tf32_split(val, hi, lo);
        float hi4 = __shfl_down_sync(0xffffffffu, hi, 4);
        float lo4 = __shfl_down_sync(0xffffffffu, lo, 4);
        if ((tx & 7) < 4) {
            int n = n0 + ty + j * 8, k = k0 + tx;
            *(float4*)&dst[(long long)n * 1024 + (k >> 3) * 16 + (tx & 3) * 4] =
                make_float4(hi, lo, hi4, lo4);
        }
    }
}

// ---------------------------------------------------------------------------
// Softmax over 512 keys, writes paired probs. One warp per row.
// ---------------------------------------------------------------------------
__global__ __launch_bounds__(256) void softmax_pack(const float* __restrict__ S,
                                                    float* __restrict__ Pp)
{
    int row  = blockIdx.x * 8 + (threadIdx.x >> 5);
    int lane = threadIdx.x & 31;
    const float* p = S + (long long)row * 512;

    float v[16];
    float m = -1e30f;
    #pragma unroll
    for (int i = 0; i < 16; i++) { v[i] = p[lane + i * 32]; m = fmaxf(m, v[i]); }
    #pragma unroll
    for (int o = 16; o > 0; o >>= 1) m = fmaxf(m, __shfl_xor_sync(0xffffffffu, m, o));
    float s = 0.f;
    #pragma unroll
    for (int i = 0; i < 16; i++) { v[i] = __expf(v[i] - m); s += v[i]; }
    #pragma unroll
    for (int o = 16; o > 0; o >>= 1) s += __shfl_xor_sync(0xffffffffu, s, o);
    float inv = 1.0f / s;

    float* outp = Pp + (long long)row * 1024;
    #pragma unroll
    for (int i = 0; i < 16; i++) {
        float pv = v[i] * inv;
        float hi, lo;
        tf32_split(pv, hi, lo);
        float hi4 = __shfl_down_sync(0xffffffffu, hi, 4);
        float lo4 = __shfl_down_sync(0xffffffffu, lo, 4);
        int col = lane + i * 32;
        if ((lane & 7) < 4)
            *(float4*)&outp[(col >> 3) * 16 + (lane & 3) * 4] =
                make_float4(hi, lo, hi4, lo4);
    }
}

// ---------------------------------------------------------------------------
// Pack crf_w/ent_w (+biases)
// ---------------------------------------------------------------------------
__global__ void prep_wpad(const float* __restrict__ crf_w, const float* __restrict__ crf_b,
                          const float* __restrict__ ent_w, const float* __restrict__ ent_b,
                          float* __restrict__ Wp, float* __restrict__ bp)
{
    int i = blockIdx.x * blockDim.x + threadIdx.x;
    int r = i >> 9, c = i & 511;
    float v = 0.f;
    if (r < 24)      v = crf_w[r * 512 + c];
    else if (r < 26) v = ent_w[(r - 24) * 512 + c];
    Wp[i] = v;
    if (c == 0) {
        float b = 0.f;
        if (r < 24)      b = crf_b[r];
        else if (r < 26) b = ent_b[r - 24];
        bp[r] = b;
    }
}

// ---------------------------------------------------------------------------
// Emissions + entity log-softmax. One warp per row.
// ---------------------------------------------------------------------------
__global__ void em_seg(const float* __restrict__ dec,
                       const float* __restrict__ Wp, const float* __restrict__ bp,
                       float* __restrict__ em, float* __restrict__ seg_out)
{
    int lane = threadIdx.x;
    int m    = blockIdx.x * blockDim.y + threadIdx.y;
    const float4* d4 = (const float4*)(dec + (long long)m * 512);
    const float4* w4 = (const float4*)(Wp + lane * 512);

    float acc = 0.f;
    #pragma unroll 8
    for (int i = 0; i < 128; i++) {
        float4 d = d4[i];
        float4 w = w4[i];
        acc = fmaf(d.x, w.x, acc);
        acc = fmaf(d.y, w.y, acc);
        acc = fmaf(d.z, w.z, acc);
        acc = fmaf(d.w, w.w, acc);
    }
    acc += bp[lane];

    if (lane < 24) em[(long long)m * 24 + lane] = acc;

    float other = __shfl_xor_sync(0xffffffffu, acc, 1);
    if (lane == 24 || lane == 25) {
        float mx  = fmaxf(acc, other);
        float lse = mx + __logf(__expf(acc - mx) + __expf(other - mx));
        seg_out[(long long)m * 2 + (lane - 24)] = acc - lse;
    }
}

// ---------------------------------------------------------------------------
// CRF numerator
// ---------------------------------------------------------------------------
__global__ void crf_num_k(const float* __restrict__ em, const int* __restrict__ labels,
                          const float* __restrict__ start_t, const float* __restrict__ end_t,
                          const float* __restrict__ trans, float* __restrict__ num)
{
    int b = blockIdx.x, tid = threadIdx.x;
    __shared__ float red[256];
    const int* lb = labels + b * 512;
    const float* emb = em + (long long)b * 512 * 24;

    float s = 0.f;
    for (int t = 1 + tid; t < 512; t += 256) {
        int prev = lb[t - 1], cur = lb[t];
        s += trans[prev * 24 + cur] + emb[t * 24 + cur];
    }
    if (tid == 0)
        s += start_t[lb[0]] + emb[lb[0]] + end_t[lb[511]];

    red[tid] = s;
    __syncthreads();
    for (int o = 128; o > 0; o >>= 1) {
        if (tid < o) red[tid] += red[tid + o];
        __syncthreads();
    }
    if (tid == 0) num[b] = red[0];
}

// ---------------------------------------------------------------------------
// Fused CRF scans: blocks 0..31 -> normalizer; blocks 32..63 -> viterbi
// ---------------------------------------------------------------------------
__global__ void crf_scan_k(const float* __restrict__ em,
                           const float* __restrict__ start_t, const float* __restrict__ end_t,
                           const float* __restrict__ trans,
                           float* __restrict__ den, float* __restrict__ out_crf)
{
    int lane = threadIdx.x;
    __shared__ float al[2][32];
    __shared__ unsigned char hist[511][24];

    if (blockIdx.x < 32) {
        int b = blockIdx.x;
        const float* emb = em + (long long)b * 512 * 24;
        float trc[24];
        if (lane < 24) {
            #pragma unroll
            for (int t = 0; t < 24; t++) trc[t] = trans[t * 24 + lane];
            al[0][lane] = start_t[lane] + emb[lane];
        }
        __syncwarp();
        int cur = 0;
        for (int s = 1; s < 512; s++) {
            float nv = 0.f;
            if (lane < 24) {
                float v[24];
                float mx = -1e30f;
                #pragma unroll
                for (int t = 0; t < 24; t++) { v[t] = al[cur][t] + trc[t]; mx = fmaxf(mx, v[t]); }
                float sum = 0.f;
                #pragma unroll
                for (int t = 0; t < 24; t++) sum += __expf(v[t] - mx);
                nv = mx + __logf(sum) + emb[s * 24 + lane];
            }
            al[cur ^ 1][lane] = nv;
            __syncwarp();
            cur ^= 1;
        }
        if (lane == 0) {
            float mx = -1e30f;
            for (int t = 0; t < 24; t++) mx = fmaxf(mx, al[cur][t] + end_t[t]);
            float sum = 0.f;
            for (int t = 0; t < 24; t++) sum += __expf(al[cur][t] + end_t[t] - mx);
            den[b] = mx + __logf(sum);
        }
    } else {
        int b = blockIdx.x - 32;
        const float* emb = em + (long long)b * 512 * 24;
        float trc[24];
        if (lane < 24) {
            #pragma unroll
            for (int t = 0; t < 24; t++) trc[t] = trans[t * 24 + lane];
            al[0][lane] = start_t[lane] + emb[lane];
        }
        __syncwarp();
        int cur = 0;
        for (int s = 1; s < 512; s++) {
            float nv = 0.f;
            if (lane < 24) {
                float best = -1e30f;
                int bi = 0;
                #pragma unroll
                for (int t = 0; t < 24; t++) {
                    float v = al[cur][t] + trc[t];
                    if (v > best) { best = v; bi = t; }
                }
                nv = best + emb[s * 24 + lane];
                hist[s - 1][lane] = (unsigned char)bi;
            }
            al[cur ^ 1][lane] = nv;
            __syncwarp();
            cur ^= 1;
        }
        if (lane == 0) {
            float best = -1e30f;
            int last = 0;
            for (int t = 0; t < 24; t++) {
                float v = al[cur][t] + end_t[t];
                if (v > best) { best = v; last = t; }
            }
            float* po = out_crf + b * 512;
            po[511] = (float)last;
            int tag = last;
            for (int i = 510; i >= 0; i--) {
                tag = hist[i][tag];
                po[i] = (float)tag;
            }
        }
    }
}

// ---------------------------------------------------------------------------
// Loss
// ---------------------------------------------------------------------------
__global__ void loss_k(const float* __restrict__ num, const float* __restrict__ den,
                       float* __restrict__ out)
{
    int lane = threadIdx.x;
    float v = num[lane] - den[lane];
    #pragma unroll
    for (int o = 16; o > 0; o >>= 1) v += __shfl_xor_sync(0xffffffffu, v, o);
    if (lane == 0) out[0] = -v / 16384.0f;
}

// ---------------------------------------------------------------------------
// Launch
// ---------------------------------------------------------------------------
extern "C" void kernel_launch(void* const* d_in, const int* in_sizes, int n_in,
                              void* d_out, int out_size)
{
    const float* enc     = (const float*)d_in[0];
    const int*   labels  = (const int*)  d_in[1];
    const float* Win     = (const float*)d_in[3];
    const float* bin_    = (const float*)d_in[4];
    const float* Wout    = (const float*)d_in[5];
    const float* bout    = (const float*)d_in[6];
    const float* crf_w   = (const float*)d_in[7];
    const float* crf_b   = (const float*)d_in[8];
    const float* start_t = (const float*)d_in[9];
    const float* end_t   = (const float*)d_in[10];
    const float* trans   = (const float*)d_in[11];
    const float* ent_w   = (const float*)d_in[12];
    const float* ent_b   = (const float*)d_in[13];
    float* out = (float*)d_out;

    float *qkv, *scores, *attn, *dec, *em, *wpad, *bpad, *num, *den;
    float *encp, *winp, *woutp, *qp, *kp, *pp, *vtp, *attnp;
    cudaGetSymbolAddress((void**)&qkv,    g_qkv);
    cudaGetSymbolAddress((void**)&scores, g_scores);
    cudaGetSymbolAddress((void**)&attn,   g_attn);
    cudaGetSymbolAddress((void**)&dec,    g_dec);
    cudaGetSymbolAddress((void**)&em,     g_em);
    cudaGetSymbolAddress((void**)&wpad,   g_wpad);
    cudaGetSymbolAddress((void**)&bpad,   g_bpad);
    cudaGetSymbolAddress((void**)&num,    g_num);
    cudaGetSymbolAddress((void**)&den,    g_den);
    cudaGetSymbolAddress((void**)&encp,   g_encp);
    cudaGetSymbolAddress((void**)&winp,   g_winp);
    cudaGetSymbolAddress((void**)&woutp,  g_woutp);
    cudaGetSymbolAddress((void**)&qp,     g_qp);
    cudaGetSymbolAddress((void**)&kp,     g_kp);
    cudaGetSymbolAddress((void**)&pp,     g_pp);
    cudaGetSymbolAddress((void**)&vtp,    g_vtp);
    cudaGetSymbolAddress((void**)&attnp,  g_attnp);

    cudaFuncSetAttribute(gemm_ps, cudaFuncAttributeMaxDynamicSharedMemorySize, GEMM_SMEM);

    // 0) weight + input packing (independent)
    prep_wpad<<<64, 256>>>(crf_w, crf_b, ent_w, ent_b, wpad, bpad);
    pack_dense<<<(Mq * 256 + 255) / 256, 256>>>(enc,  encp,  Mq * 256);
    pack_dense<<<(1536 * 256 + 255) / 256, 256>>>(Win,  winp,  1536 * 256);
    pack_dense<<<(512 * 256 + 255) / 256, 256>>>(Wout, woutp, 512 * 256);

    // 1) QKV = enc @ Win^T + bin_   (16384 x 1536, K=512)
    gemm_ps<<<dim3(12, 128, 1), 256, GEMM_SMEM>>>(
        encp, 0, 0,
        winp, 0, 0,
        bin_,
        qkv, 3 * Eq, 0, 0,
        Eq, 1.0f, 0, 1);

    // 1b) pack Q,K views; transpose+pack V
    pack_qk<<<16384, 256>>>(qkv, qp, kp);
    transpose_vp<<<dim3(16, 8, Bq * Hq), dim3(32, 8)>>>(qkv, vtp);

    // 2) scores = Q @ K^T / 16   (per bh: 512x512, K=256)
    gemm_ps<<<dim3(4, 4, Bq * Hq), 256, GEMM_SMEM>>>(
        qp, (long long)Sq * 2 * HDq, 0,
        kp, (long long)Sq * 2 * HDq, 0,
        nullptr,
        scores, Sq, (long long)Sq * Sq, 0,
        HDq, 0.0625f, 0, 1);

    // 3) softmax -> paired probs
    softmax_pack<<<(Bq * Hq * Sq) / 8, 256>>>(scores, pp);

    // 4) attn = P @ V   (per bh: 512x256, K=512)
    gemm_ps<<<dim3(2, 4, Bq * Hq), 256, GEMM_SMEM>>>(
        pp,  (long long)Hq * Sq * 2 * Sq, (long long)Sq * 2 * Sq,
        vtp, (long long)Hq * HDq * 2 * Sq, (long long)HDq * 2 * Sq,
        nullptr,
        attn, Eq, (long long)Sq * Eq, HDq,
        Sq, 1.0f, 0, Hq);

    // 4b) pack attn for output projection
    pack_dense<<<(Mq * 256 + 255) / 256, 256>>>(attn, attnp, Mq * 256);

    // 5) dec = relu(attn @ Wout^T + bout)
    gemm_ps<<<dim3(4, 128, 1), 256, GEMM_SMEM>>>(
        attnp, 0, 0,
        woutp, 0, 0,
        bout,
        dec, Eq, 0, 0,
        Eq, 1.0f, 1, 1);

    // 6) emissions + entity log-softmax
    em_seg<<<Mq / 8, dim3(32, 8)>>>(dec, wpad, bpad, em, out + Mq);

    // 7) CRF
    crf_num_k<<<Bq, 256>>>(em, labels, start_t, end_t, trans, num);
    crf_scan_k<<<2 * Bq, 32>>>(em, start_t, end_t, trans, den, out);

    // 8) loss
    loss_k<<<1, 32>>>(num, den, out + Mq + 2 * Mq);
}

// round 13
// speedup vs baseline: 1.1333x; 1.1333x over previous
#include <cuda_runtime.h>
#include <cstdint>
#include <math.h>

// ---------------------------------------------------------------------------
// Problem constants
// ---------------------------------------------------------------------------
#define Bq   32
#define Sq   512
#define Eq   512
#define Tq   24
#define Hq   2
#define HDq  256
#define Mq   (Bq*Sq)      // 16384

// ---------------------------------------------------------------------------
// Scratch
// ---------------------------------------------------------------------------
__device__ float g_qkv   [Mq * 3 * Eq];
__device__ float g_vt    [Bq * Hq * HDq * Sq];
__device__ float g_scores[Bq * Hq * Sq * Sq];
__device__ float g_attn  [Mq * Eq];
__device__ float g_dec   [Mq * Eq];
__device__ float g_em    [Mq * Tq];
__device__ float g_wpad  [32 * Eq];
__device__ float g_bpad  [32];
__device__ float g_num   [Bq];
__device__ float g_den   [Bq];

// ---------------------------------------------------------------------------
// Helpers
// ---------------------------------------------------------------------------
__device__ __forceinline__ void tf32_split(float x, float& h, float& l) {
    asm("cvt.rna.tf32.f32 %0, %1;" : "=f"(h) : "f"(x));
    float d = x - h;
    asm("cvt.rna.tf32.f32 %0, %1;" : "=f"(l) : "f"(d));
}

__device__ __forceinline__ uint32_t smem_u32(const void* p) {
    uint32_t a;
    asm("{ .reg .u64 t; cvta.to.shared.u64 t, %1; cvt.u32.u64 %0, t; }" : "=r"(a) : "l"(p));
    return a;
}

__device__ __forceinline__ void cpa16(uint32_t s, const void* g) {
    asm volatile("cp.async.cg.shared.global [%0], [%1], 16;" :: "r"(s), "l"(g));
}

#define MMA_TF32(c, a0, a1, a2, a3, b0, b1) \
    asm volatile("mma.sync.aligned.m16n8k8.row.col.f32.tf32.tf32.f32 " \
        "{%0,%1,%2,%3}, {%4,%5,%6,%7}, {%8,%9}, {%0,%1,%2,%3};" \
        : "+f"((c)[0]), "+f"((c)[1]), "+f"((c)[2]), "+f"((c)[3]) \
        : "r"(__float_as_uint(a0)), "r"(__float_as_uint(a1)), \
          "r"(__float_as_uint(a2)), "r"(__float_as_uint(a3)), \
          "r"(__float_as_uint(b0)), "r"(__float_as_uint(b1)))

// ---------------------------------------------------------------------------
// 3xTF32 NT GEMM: C[M,N] = alpha*(A[M,K] @ B[N,K]^T) (+bias)(+relu)
// BM=256, BN=128, BK=32, 512 threads (16 warps, 4x4 grid, 64x32 per warp).
// cp.async stages RAW fp32 tiles (stride 36, conflict-free); threads read
// back their OWN chunks, split to hi/lo tiles (stride 36, R3-verified
// conflict-free fragment loads), then MMA. Next-tile cp.async is issued
// right after the read barrier so its latency hides under split+MMA.
// ---------------------------------------------------------------------------
#define BM 256
#define BN 128
#define BK 32
#define TSTRIDE 36
#define RAWA   (BM * TSTRIDE)             // 9216 floats
#define RAWB   (BN * TSTRIDE)             // 4608
#define OFF_AH (RAWA + RAWB)              // 13824
#define SPLITA (BM * TSTRIDE)
#define SPLITB (BN * TSTRIDE)
#define OFF_AL (OFF_AH + SPLITA)
#define OFF_BH (OFF_AL + SPLITA)
#define OFF_BL (OFF_BH + SPLITB)
#define SMEMF  (OFF_BL + SPLITB)          // 41472 floats
#define GEMM_SMEM (SMEMF * 4)             // 165888 bytes

__global__ __launch_bounds__(512, 1) void gemm_mma(
    const float* __restrict__ A, int lda, long long sAb, long long sAh,
    const float* __restrict__ B, int ldb, long long sBb, long long sBh,
    const float* __restrict__ bias,
    float* __restrict__ C, int ldc, long long sCb, long long sCh,
    int K, float alpha, int relu, int H)
{
    extern __shared__ float smem[];
    uint32_t sb0 = smem_u32(smem);
    int tid = threadIdx.x, wid = tid >> 5, lane = tid & 31;
    int wm = wid & 3, wn = wid >> 2;          // 4 x 4 warp grid
    int gq = lane >> 2, gr = lane & 3;

    int z = blockIdx.z, zb = z / H, zh = z - zb * H;
    A += (long long)zb * sAb + (long long)zh * sAh;
    B += (long long)zb * sBb + (long long)zh * sBh;
    C += (long long)zb * sCb + (long long)zh * sCh;
    int bm = blockIdx.y * BM, bn = blockIdx.x * BN;

    // copy mapping: A: each thread 16 floats (4 chunks); B: each thread 8 (2)
    int arow = tid >> 1, acol = (tid & 1) << 4;
    int brow = tid >> 2, bcol = (tid & 3) << 3;
    const float* gA = A + (long long)(bm + arow) * lda + acol;
    const float* gB = B + (long long)(bn + brow) * ldb + bcol;
    uint32_t rA = sb0 + (uint32_t)(arow * TSTRIDE + acol) * 4u;
    uint32_t rB = sb0 + (uint32_t)(RAWA + brow * TSTRIDE + bcol) * 4u;

    float* Ahs = smem + OFF_AH;
    float* Als = smem + OFF_AL;
    float* Bhs = smem + OFF_BH;
    float* Bls = smem + OFF_BL;

    float acc[4][4][4];
    #pragma unroll
    for (int mi = 0; mi < 4; mi++)
        #pragma unroll
        for (int ni = 0; ni < 4; ni++)
            #pragma unroll
            for (int q = 0; q < 4; q++) acc[mi][ni][q] = 0.f;

    int nK = K >> 5;

    // prologue: raw tile 0
    #pragma unroll
    for (int i = 0; i < 4; i++) cpa16(rA + i * 16, gA + i * 4);
    #pragma unroll
    for (int i = 0; i < 2; i++) cpa16(rB + i * 16, gB + i * 4);
    asm volatile("cp.async.commit_group;");

    for (int kt = 0; kt < nK; kt++) {
        asm volatile("cp.async.wait_group 0;");
        // read back own raw chunks (no cross-thread deps)
        float4 av[4], bv[2];
        {
            const float* rawa = smem + arow * TSTRIDE + acol;
            const float* rawb = smem + RAWA + brow * TSTRIDE + bcol;
            #pragma unroll
            for (int i = 0; i < 4; i++) av[i] = *(const float4*)(rawa + i * 4);
            #pragma unroll
            for (int i = 0; i < 2; i++) bv[i] = *(const float4*)(rawb + i * 4);
        }
        __syncthreads();   // all raw reads done AND prev MMA done

        if (kt + 1 < nK) {
            int kb = (kt + 1) << 5;
            #pragma unroll
            for (int i = 0; i < 4; i++) cpa16(rA + i * 16, gA + kb + i * 4);
            #pragma unroll
            for (int i = 0; i < 2; i++) cpa16(rB + i * 16, gB + kb + i * 4);
            asm volatile("cp.async.commit_group;");
        }

        // split -> hi/lo tiles
        #pragma unroll
        for (int i = 0; i < 4; i++) {
            float4 h, l;
            tf32_split(av[i].x, h.x, l.x); tf32_split(av[i].y, h.y, l.y);
            tf32_split(av[i].z, h.z, l.z); tf32_split(av[i].w, h.w, l.w);
            *(float4*)&Ahs[arow * TSTRIDE + acol + i * 4] = h;
            *(float4*)&Als[arow * TSTRIDE + acol + i * 4] = l;
        }
        #pragma unroll
        for (int i = 0; i < 2; i++) {
            float4 h, l;
            tf32_split(bv[i].x, h.x, l.x); tf32_split(bv[i].y, h.y, l.y);
            tf32_split(bv[i].z, h.z, l.z); tf32_split(bv[i].w, h.w, l.w);
            *(float4*)&Bhs[brow * TSTRIDE + bcol + i * 4] = h;
            *(float4*)&Bls[brow * TSTRIDE + bcol + i * 4] = l;
        }
        __syncthreads();

        // MMA phase (R3-verified fragment scheme)
        #pragma unroll
        for (int ks = 0; ks < 4; ks++) {
            int k0 = (ks << 3) + gr;
            float bh0[4], bh1[4], bl0[4], bl1[4];
            #pragma unroll
            for (int ni = 0; ni < 4; ni++) {
                int rb = (wn * 32 + ni * 8 + gq) * TSTRIDE + k0;
                bh0[ni] = Bhs[rb]; bh1[ni] = Bhs[rb + 4];
                bl0[ni] = Bls[rb]; bl1[ni] = Bls[rb + 4];
            }
            #pragma unroll
            for (int mi = 0; mi < 4; mi++) {
                int ra = (wm * 64 + mi * 16 + gq) * TSTRIDE + k0;
                float ah0 = Ahs[ra], ah1 = Ahs[ra + 8 * TSTRIDE];
                float ah2 = Ahs[ra + 4], ah3 = Ahs[ra + 8 * TSTRIDE + 4];
                float al0 = Als[ra], al1 = Als[ra + 8 * TSTRIDE];
                float al2 = Als[ra + 4], al3 = Als[ra + 8 * TSTRIDE + 4];
                #pragma unroll
                for (int ni = 0; ni < 4; ni++)
                    MMA_TF32(acc[mi][ni], ah0, ah1, ah2, ah3, bh0[ni], bh1[ni]);
                #pragma unroll
                for (int ni = 0; ni < 4; ni++)
                    MMA_TF32(acc[mi][ni], ah0, ah1, ah2, ah3, bl0[ni], bl1[ni]);
                #pragma unroll
                for (int ni = 0; ni < 4; ni++)
                    MMA_TF32(acc[mi][ni], al0, al1, al2, al3, bh0[ni], bh1[ni]);
            }
        }
        __syncthreads();
    }

    // Epilogue: accs -> smem -> coalesced gmem
    float* Cst = smem;
    #pragma unroll
    for (int mi = 0; mi < 4; mi++) {
        int row = wm * 64 + mi * 16 + gq;
        #pragma unroll
        for (int ni = 0; ni < 4; ni++) {
            int col = wn * 32 + ni * 8 + gr * 2;
            Cst[row * 132 + col]           = acc[mi][ni][0];
            Cst[row * 132 + col + 1]       = acc[mi][ni][1];
            Cst[(row + 8) * 132 + col]     = acc[mi][ni][2];
            Cst[(row + 8) * 132 + col + 1] = acc[mi][ni][3];
        }
    }
    __syncthreads();

    for (int idx = tid; idx < BM * BN / 4; idx += 512) {
        int r2 = idx >> 5, c4 = (idx & 31) << 2;
        float4 v = *(float4*)&Cst[r2 * 132 + c4];
        v.x *= alpha; v.y *= alpha; v.z *= alpha; v.w *= alpha;
        if (bias) {
            float4 bb = *(const float4*)&bias[bn + c4];
            v.x += bb.x; v.y += bb.y; v.z += bb.z; v.w += bb.w;
        }
        if (relu) {
            v.x = fmaxf(v.x, 0.f); v.y = fmaxf(v.y, 0.f);
            v.z = fmaxf(v.z, 0.f); v.w = fmaxf(v.w, 0.f);
        }
        *(float4*)&C[(long long)(bm + r2) * ldc + bn + c4] = v;
    }
}

// ---------------------------------------------------------------------------
// V transpose: vt[bh][n][k] = qkv[b][k][2E + h*HD + n]
// ---------------------------------------------------------------------------
__global__ void transpose_v(const float* __restrict__ qkv, float* __restrict__ vt)
{
    __shared__ float t[32][33];
    int z = blockIdx.z, zb = z >> 1, zh = z & 1;
    const float* src = qkv + (long long)zb * Sq * 3 * Eq + 2 * Eq + zh * HDq;
    float* dst = vt + (long long)z * HDq * Sq;
    int k0 = blockIdx.x * 32, n0 = blockIdx.y * 32;
    int tx = threadIdx.x, ty = threadIdx.y;
    #pragma unroll
    for (int j = 0; j < 4; j++)
        t[ty + j * 8][tx] = src[(long long)(k0 + ty + j * 8) * (3 * Eq) + n0 + tx];
    __syncthreads();
    #pragma unroll
    for (int j = 0; j < 4; j++)
        dst[(long long)(n0 + ty + j * 8) * Sq + k0 + tx] = t[tx][ty + j * 8];
}

// ---------------------------------------------------------------------------
// Row softmax over 512 columns. One warp per row.
// ---------------------------------------------------------------------------
__global__ __launch_bounds__(256) void softmax_rows(float* __restrict__ S)
{
    int row  = blockIdx.x * 8 + (threadIdx.x >> 5);
    int lane = threadIdx.x & 31;
    float* p = S + (long long)row * 512;

    float v[16];
    float m = -1e30f;
    #pragma unroll
    for (int i = 0; i < 16; i++) { v[i] = p[lane + i * 32]; m = fmaxf(m, v[i]); }
    #pragma unroll
    for (int o = 16; o > 0; o >>= 1) m = fmaxf(m, __shfl_xor_sync(0xffffffffu, m, o));
    float s = 0.f;
    #pragma unroll
    for (int i = 0; i < 16; i++) { v[i] = __expf(v[i] - m); s += v[i]; }
    #pragma unroll
    for (int o = 16; o > 0; o >>= 1) s += __shfl_xor_sync(0xffffffffu, s, o);
    float inv = 1.0f / s;
    #pragma unroll
    for (int i = 0; i < 16; i++) p[lane + i * 32] = v[i] * inv;
}

// ---------------------------------------------------------------------------
// Pack crf_w/ent_w (+biases)
// ---------------------------------------------------------------------------
__global__ void prep_wpad(const float* __restrict__ crf_w, const float* __restrict__ crf_b,
                          const float* __restrict__ ent_w, const float* __restrict__ ent_b,
                          float* __restrict__ Wp, float* __restrict__ bp)
{
    int i = blockIdx.x * blockDim.x + threadIdx.x;
    int r = i >> 9, c = i & 511;
    float v = 0.f;
    if (r < 24)      v = crf_w[r * 512 + c];
    else if (r < 26) v = ent_w[(r - 24) * 512 + c];
    Wp[i] = v;
    if (c == 0) {
        float b = 0.f;
        if (r < 24)      b = crf_b[r];
        else if (r < 26) b = ent_b[r - 24];
        bp[r] = b;
    }
}

// ---------------------------------------------------------------------------
// Emissions + entity log-softmax. One warp per row; loop over 26 outputs
// with COALESCED k-interleaved weight loads + butterfly reduction.
// ---------------------------------------------------------------------------
__global__ void em_seg(const float* __restrict__ dec,
                       const float* __restrict__ Wp, const float* __restrict__ bp,
                       float* __restrict__ em, float* __restrict__ seg_out)
{
    int lane = threadIdx.x;
    int m    = blockIdx.x * blockDim.y + threadIdx.y;
    const float4* d4 = (const float4*)(dec + (long long)m * 512);

    float4 d[4];
    #pragma unroll
    for (int i = 0; i < 4; i++) d[i] = d4[i * 32 + lane];

    float s24 = 0.f, s25 = 0.f;
    #pragma unroll
    for (int t = 0; t < 26; t++) {
        const float4* w4 = (const float4*)(Wp + t * 512);
        float acc = 0.f;
        #pragma unroll
        for (int i = 0; i < 4; i++) {
            float4 w = w4[i * 32 + lane];
            acc = fmaf(d[i].x, w.x, acc);
            acc = fmaf(d[i].y, w.y, acc);
            acc = fmaf(d[i].z, w.z, acc);
            acc = fmaf(d[i].w, w.w, acc);
        }
        #pragma unroll
        for (int o = 16; o > 0; o >>= 1) acc += __shfl_xor_sync(0xffffffffu, acc, o);
        acc += bp[t];
        if (t < 24) {
            if (lane == t) em[(long long)m * 24 + t] = acc;
        } else if (t == 24) s24 = acc;
        else s25 = acc;
    }
    if (lane == 0) {
        float mx  = fmaxf(s24, s25);
        float lse = mx + __logf(__expf(s24 - mx) + __expf(s25 - mx));
        seg_out[(long long)m * 2 + 0] = s24 - lse;
        seg_out[(long long)m * 2 + 1] = s25 - lse;
    }
}

// ---------------------------------------------------------------------------
// CRF numerator
// ---------------------------------------------------------------------------
__global__ void crf_num_k(const float* __restrict__ em, const int* __restrict__ labels,
                          const float* __restrict__ start_t, const float* __restrict__ end_t,
                          const float* __restrict__ trans, float* __restrict__ num)
{
    int b = blockIdx.x, tid = threadIdx.x;
    __shared__ float red[256];
    const int* lb = labels + b * 512;
    const float* emb = em + (long long)b * 512 * 24;

    float s = 0.f;
    for (int t = 1 + tid; t < 512; t += 256) {
        int prev = lb[t - 1], cur = lb[t];
        s += trans[prev * 24 + cur] + emb[t * 24 + cur];
    }
    if (tid == 0)
        s += start_t[lb[0]] + emb[lb[0]] + end_t[lb[511]];

    red[tid] = s;
    __syncthreads();
    for (int o = 128; o > 0; o >>= 1) {
        if (tid < o) red[tid] += red[tid + o];
        __syncthreads();
    }
    if (tid == 0) num[b] = red[0];
}

// ---------------------------------------------------------------------------
// Fused CRF scans: blocks 0..31 -> normalizer; blocks 32..63 -> viterbi
// ---------------------------------------------------------------------------
__global__ void crf_scan_k(const float* __restrict__ em,
                           const float* __restrict__ start_t, const float* __restrict__ end_t,
                           const float* __restrict__ trans,
                           float* __restrict__ den, float* __restrict__ out_crf)
{
    int lane = threadIdx.x;
    __shared__ float al[2][32];
    __shared__ unsigned char hist[511][24];

    if (blockIdx.x < 32) {
        int b = blockIdx.x;
        const float* emb = em + (long long)b * 512 * 24;
        float trc[24];
        if (lane < 24) {
            #pragma unroll
            for (int t = 0; t < 24; t++) trc[t] = trans[t * 24 + lane];
            al[0][lane] = start_t[lane] + emb[lane];
        }
        __syncwarp();
        int cur = 0;
        for (int s = 1; s < 512; s++) {
            float nv = 0.f;
            if (lane < 24) {
                float v[24];
                float mx = -1e30f;
                #pragma unroll
                for (int t = 0; t < 24; t++) { v[t] = al[cur][t] + trc[t]; mx = fmaxf(mx, v[t]); }
                float sum = 0.f;
                #pragma unroll
                for (int t = 0; t < 24; t++) sum += __expf(v[t] - mx);
                nv = mx + __logf(sum) + emb[s * 24 + lane];
            }
            al[cur ^ 1][lane] = nv;
            __syncwarp();
            cur ^= 1;
        }
        if (lane == 0) {
            float mx = -1e30f;
            for (int t = 0; t < 24; t++) mx = fmaxf(mx, al[cur][t] + end_t[t]);
            float sum = 0.f;
            for (int t = 0; t < 24; t++) sum += __expf(al[cur][t] + end_t[t] - mx);
            den[b] = mx + __logf(sum);
        }
    } else {
        int b = blockIdx.x - 32;
        const float* emb = em + (long long)b * 512 * 24;
        float trc[24];
        if (lane < 24) {
            #pragma unroll
            for (int t = 0; t < 24; t++) trc[t] = trans[t * 24 + lane];
            al[0][lane] = start_t[lane] + emb[lane];
        }
        __syncwarp();
        int cur = 0;
        for (int s = 1; s < 512; s++) {
            float nv = 0.f;
            if (lane < 24) {
                float best = -1e30f;
                int bi = 0;
                #pragma unroll
                for (int t = 0; t < 24; t++) {
                    float v = al[cur][t] + trc[t];
                    if (v > best) { best = v; bi = t; }
                }
                nv = best + emb[s * 24 + lane];
                hist[s - 1][lane] = (unsigned char)bi;
            }
            al[cur ^ 1][lane] = nv;
            __syncwarp();
            cur ^= 1;
        }
        if (lane == 0) {
            float best = -1e30f;
            int last = 0;
            for (int t = 0; t < 24; t++) {
                float v = al[cur][t] + end_t[t];
                if (v > best) { best = v; last = t; }
            }
            float* po = out_crf + b * 512;
            po[511] = (float)last;
            int tag = last;
            for (int i = 510; i >= 0; i--) {
                tag = hist[i][tag];
                po[i] = (float)tag;
            }
        }
    }
}

// ---------------------------------------------------------------------------
// Loss
// ---------------------------------------------------------------------------
__global__ void loss_k(const float* __restrict__ num, const float* __restrict__ den,
                       float* __restrict__ out)
{
    int lane = threadIdx.x;
    float v = num[lane] - den[lane];
    #pragma unroll
    for (int o = 16; o > 0; o >>= 1) v += __shfl_xor_sync(0xffffffffu, v, o);
    if (lane == 0) out[0] = -v / 16384.0f;
}

// ---------------------------------------------------------------------------
// Launch
// ---------------------------------------------------------------------------
extern "C" void kernel_launch(void* const* d_in, const int* in_sizes, int n_in,
                              void* d_out, int out_size)
{
    const float* enc     = (const float*)d_in[0];
    const int*   labels  = (const int*)  d_in[1];
    const float* Win     = (const float*)d_in[3];
    const float* bin_    = (const float*)d_in[4];
    const float* Wout    = (const float*)d_in[5];
    const float* bout    = (const float*)d_in[6];
    const float* crf_w   = (const float*)d_in[7];
    const float* crf_b   = (const float*)d_in[8];
    const float* start_t = (const float*)d_in[9];
    const float* end_t   = (const float*)d_in[10];
    const float* trans   = (const float*)d_in[11];
    const float* ent_w   = (const float*)d_in[12];
    const float* ent_b   = (const float*)d_in[13];
    float* out = (float*)d_out;

    float *qkv, *vt, *scores, *attn, *dec, *em, *wpad, *bpad, *num, *den;
    cudaGetSymbolAddress((void**)&qkv,    g_qkv);
    cudaGetSymbolAddress((void**)&vt,     g_vt);
    cudaGetSymbolAddress((void**)&scores, g_scores);
    cudaGetSymbolAddress((void**)&attn,   g_attn);
    cudaGetSymbolAddress((void**)&dec,    g_dec);
    cudaGetSymbolAddress((void**)&em,     g_em);
    cudaGetSymbolAddress((void**)&wpad,   g_wpad);
    cudaGetSymbolAddress((void**)&bpad,   g_bpad);
    cudaGetSymbolAddress((void**)&num,    g_num);
    cudaGetSymbolAddress((void**)&den,    g_den);

    cudaFuncSetAttribute(gemm_mma, cudaFuncAttributeMaxDynamicSharedMemorySize, GEMM_SMEM);

    prep_wpad<<<64, 256>>>(crf_w, crf_b, ent_w, ent_b, wpad, bpad);

    // 1) QKV = enc @ Win^T + bin_   (16384 x 1536, K=512)
    gemm_mma<<<dim3(12, 64, 1), 512, GEMM_SMEM>>>(
        enc, Eq, 0, 0,
        Win, Eq, 0, 0,
        bin_,
        qkv, 3 * Eq, 0, 0,
        Eq, 1.0f, 0, 1);

    // 1b) V transpose for NT attnV
    transpose_v<<<dim3(16, 8, Bq * Hq), dim3(32, 8)>>>(qkv, vt);

    // 2) scores = Q @ K^T / 16   (per bh: 512x512, K=256)
    gemm_mma<<<dim3(4, 2, Bq * Hq), 512, GEMM_SMEM>>>(
        qkv,      3 * Eq, (long long)Sq * 3 * Eq, HDq,
        qkv + Eq, 3 * Eq, (long long)Sq * 3 * Eq, HDq,
        nullptr,
        scores, Sq, (long long)Hq * Sq * Sq, (long long)Sq * Sq,
        HDq, 0.0625f, 0, Hq);

    // 3) softmax
    softmax_rows<<<(Bq * Hq * Sq) / 8, 256>>>(scores);

    // 4) attn = P @ V   (per bh: 512x256, K=512) via NT with vt
    gemm_mma<<<dim3(2, 2, Bq * Hq), 512, GEMM_SMEM>>>(
        scores, Sq, (long long)Hq * Sq * Sq, (long long)Sq * Sq,
        vt,     Sq, (long long)Hq * HDq * Sq, (long long)HDq * Sq,
        nullptr,
        attn, Eq, (long long)Sq * Eq, HDq,
        Sq, 1.0f, 0, Hq);

    // 5) dec = relu(attn @ Wout^T + bout)
    gemm_mma<<<dim3(4, 64, 1), 512, GEMM_SMEM>>>(
        attn, Eq, 0, 0,
        Wout, Eq, 0, 0,
        bout,
        dec, Eq, 0, 0,
        Eq, 1.0f, 1, 1);

    // 6) emissions + entity log-softmax
    em_seg<<<Mq / 8, dim3(32, 8)>>>(dec, wpad, bpad, em, out + Mq);

    // 7) CRF
    crf_num_k<<<Bq, 256>>>(em, labels, start_t, end_t, trans, num);
    crf_scan_k<<<2 * Bq, 32>>>(em, start_t, end_t, trans, den, out);

    // 8) loss
    loss_k<<<1, 32>>>(num, den, out + Mq + 2 * Mq);
}

// round 16
// speedup vs baseline: 1.2396x; 1.0938x over previous
#include <cuda_runtime.h>
#include <cstdint>
#include <math.h>

// ---------------------------------------------------------------------------
// Problem constants
// ---------------------------------------------------------------------------
#define Bq   32
#define Sq   512
#define Eq   512
#define Tq   24
#define Hq   2
#define HDq  256
#define Mq   (Bq*Sq)      // 16384

// ---------------------------------------------------------------------------
// Scratch
// ---------------------------------------------------------------------------
__device__ float g_qkv   [Mq * 3 * Eq];
__device__ float g_vt    [Bq * Hq * HDq * Sq];
__device__ float g_scores[Bq * Hq * Sq * Sq];
__device__ float g_attn  [Mq * Eq];
__device__ float g_dec   [Mq * Eq];
__device__ float g_em    [Mq * Tq];
__device__ float g_wpad  [32 * Eq];
__device__ float g_bpad  [32];
__device__ float g_num   [Bq];
__device__ float g_den   [Bq];

// ---------------------------------------------------------------------------
// Helpers
// ---------------------------------------------------------------------------
__device__ __forceinline__ void tf32_split(float x, float& h, float& l) {
    asm("cvt.rna.tf32.f32 %0, %1;" : "=f"(h) : "f"(x));
    float d = x - h;
    asm("cvt.rna.tf32.f32 %0, %1;" : "=f"(l) : "f"(d));
}

#define MMA_TF32(c, a0, a1, a2, a3, b0, b1) \
    asm volatile("mma.sync.aligned.m16n8k8.row.col.f32.tf32.tf32.f32 " \
        "{%0,%1,%2,%3}, {%4,%5,%6,%7}, {%8,%9}, {%0,%1,%2,%3};" \
        : "+f"((c)[0]), "+f"((c)[1]), "+f"((c)[2]), "+f"((c)[3]) \
        : "r"(__float_as_uint(a0)), "r"(__float_as_uint(a1)), \
          "r"(__float_as_uint(a2)), "r"(__float_as_uint(a3)), \
          "r"(__float_as_uint(b0)), "r"(__float_as_uint(b1)))

// ---------------------------------------------------------------------------
// 3xTF32 NT GEMM: C[M,N] = alpha*(A[M,K] @ B[N,K]^T) (+bias)(+relu)
// BM=256, BN=128, BK=32, 512 threads (4x4 warps, 64x32 per warp).
// gmem->register pipelined LDG (2 tiles ahead); hi/lo split tiles
// DOUBLE-BUFFERED in smem; ONE __syncthreads per k-tile:
//   iter kt: split regs(kt+1)->stage[kt+1]; LDG(kt+2)->regs; MMA stage[kt]; bar.
// ---------------------------------------------------------------------------
#define BM 256
#define BN 128
#define TSTRIDE 36
#define AHS 0
#define ALS (BM * TSTRIDE)                    // 9216
#define BHS (2 * BM * TSTRIDE)                // 18432
#define BLS (2 * BM * TSTRIDE + BN * TSTRIDE) // 23040
#define STAGE (2 * (BM + BN) * TSTRIDE)       // 27648 floats
#define GEMM_SMEM (2 * STAGE * 4)             // 221184 bytes

__global__ __launch_bounds__(512, 1) void gemm_mma(
    const float* __restrict__ A, int lda, long long sAb, long long sAh,
    const float* __restrict__ B, int ldb, long long sBb, long long sBh,
    const float* __restrict__ bias,
    float* __restrict__ C, int ldc, long long sCb, long long sCh,
    int K, float alpha, int relu, int H)
{
    extern __shared__ float smem[];
    int tid = threadIdx.x, wid = tid >> 5, lane = tid & 31;
    int wm = wid & 3, wn = wid >> 2;          // 4 x 4 warp grid
    int gq = lane >> 2, gr = lane & 3;

    int z = blockIdx.z, zb = z / H, zh = z - zb * H;
    A += (long long)zb * sAb + (long long)zh * sAh;
    B += (long long)zb * sBb + (long long)zh * sBh;
    C += (long long)zb * sCb + (long long)zh * sCh;
    int bm = blockIdx.y * BM, bn = blockIdx.x * BN;

    // copy mapping: A: 16 floats/thread; B: 8 floats/thread
    int arow = tid >> 1, acol = (tid & 1) << 4;
    int brow = tid >> 2, bcol = (tid & 3) << 3;
    const float* gA = A + (long long)(bm + arow) * lda + acol;
    const float* gB = B + (long long)(bn + brow) * ldb + bcol;

    float acc[4][4][4];
    #pragma unroll
    for (int mi = 0; mi < 4; mi++)
        #pragma unroll
        for (int ni = 0; ni < 4; ni++)
            #pragma unroll
            for (int q = 0; q < 4; q++) acc[mi][ni][q] = 0.f;

    int nK = K >> 5;
    float4 av[4], bv[2];

    // prologue: tile 0 -> regs -> split into stage 0; then load tile 1
    #pragma unroll
    for (int i = 0; i < 4; i++) av[i] = *(const float4*)(gA + i * 4);
    #pragma unroll
    for (int i = 0; i < 2; i++) bv[i] = *(const float4*)(gB + i * 4);
    {
        float* st = smem;
        #pragma unroll
        for (int i = 0; i < 4; i++) {
            float4 h, l;
            tf32_split(av[i].x, h.x, l.x); tf32_split(av[i].y, h.y, l.y);
            tf32_split(av[i].z, h.z, l.z); tf32_split(av[i].w, h.w, l.w);
            *(float4*)&st[AHS + arow * TSTRIDE + acol + i * 4] = h;
            *(float4*)&st[ALS + arow * TSTRIDE + acol + i * 4] = l;
        }
        #pragma unroll
        for (int i = 0; i < 2; i++) {
            float4 h, l;
            tf32_split(bv[i].x, h.x, l.x); tf32_split(bv[i].y, h.y, l.y);
            tf32_split(bv[i].z, h.z, l.z); tf32_split(bv[i].w, h.w, l.w);
            *(float4*)&st[BHS + brow * TSTRIDE + bcol + i * 4] = h;
            *(float4*)&st[BLS + brow * TSTRIDE + bcol + i * 4] = l;
        }
    }
    if (nK > 1) {
        #pragma unroll
        for (int i = 0; i < 4; i++) av[i] = *(const float4*)(gA + 32 + i * 4);
        #pragma unroll
        for (int i = 0; i < 2; i++) bv[i] = *(const float4*)(gB + 32 + i * 4);
    }
    __syncthreads();

    for (int kt = 0; kt < nK; kt++) {
        // 1) split regs(kt+1) -> stage[(kt+1)&1]
        if (kt + 1 < nK) {
            float* st = smem + ((kt + 1) & 1) * STAGE;
            #pragma unroll
            for (int i = 0; i < 4; i++) {
                float4 h, l;
                tf32_split(av[i].x, h.x, l.x); tf32_split(av[i].y, h.y, l.y);
                tf32_split(av[i].z, h.z, l.z); tf32_split(av[i].w, h.w, l.w);
                *(float4*)&st[AHS + arow * TSTRIDE + acol + i * 4] = h;
                *(float4*)&st[ALS + arow * TSTRIDE + acol + i * 4] = l;
            }
            #pragma unroll
            for (int i = 0; i < 2; i++) {
                float4 h, l;
                tf32_split(bv[i].x, h.x, l.x); tf32_split(bv[i].y, h.y, l.y);
                tf32_split(bv[i].z, h.z, l.z); tf32_split(bv[i].w, h.w, l.w);
                *(float4*)&st[BHS + brow * TSTRIDE + bcol + i * 4] = h;
                *(float4*)&st[BLS + brow * TSTRIDE + bcol + i * 4] = l;
            }
        }
        // 2) LDG tile kt+2 -> regs (in flight under MMA)
        if (kt + 2 < nK) {
            int kb = (kt + 2) << 5;
            #pragma unroll
            for (int i = 0; i < 4; i++) av[i] = *(const float4*)(gA + kb + i * 4);
            #pragma unroll
            for (int i = 0; i < 2; i++) bv[i] = *(const float4*)(gB + kb + i * 4);
        }
        // 3) MMA over stage[kt&1]
        {
            const float* Ahs = smem + (kt & 1) * STAGE + AHS;
            const float* Als = smem + (kt & 1) * STAGE + ALS;
            const float* Bhs = smem + (kt & 1) * STAGE + BHS;
            const float* Bls = smem + (kt & 1) * STAGE + BLS;
            #pragma unroll
            for (int ks = 0; ks < 4; ks++) {
                int k0 = (ks << 3) + gr;
                float bh0[4], bh1[4], bl0[4], bl1[4];
                #pragma unroll
                for (int ni = 0; ni < 4; ni++) {
                    int rb = (wn * 32 + ni * 8 + gq) * TSTRIDE + k0;
                    bh0[ni] = Bhs[rb]; bh1[ni] = Bhs[rb + 4];
                    bl0[ni] = Bls[rb]; bl1[ni] = Bls[rb + 4];
                }
                #pragma unroll
                for (int mi = 0; mi < 4; mi++) {
                    int ra = (wm * 64 + mi * 16 + gq) * TSTRIDE + k0;
                    float ah0 = Ahs[ra], ah1 = Ahs[ra + 8 * TSTRIDE];
                    float ah2 = Ahs[ra + 4], ah3 = Ahs[ra + 8 * TSTRIDE + 4];
                    float al0 = Als[ra], al1 = Als[ra + 8 * TSTRIDE];
                    float al2 = Als[ra + 4], al3 = Als[ra + 8 * TSTRIDE + 4];
                    #pragma unroll
                    for (int ni = 0; ni < 4; ni++)
                        MMA_TF32(acc[mi][ni], ah0, ah1, ah2, ah3, bh0[ni], bh1[ni]);
                    #pragma unroll
                    for (int ni = 0; ni < 4; ni++)
                        MMA_TF32(acc[mi][ni], ah0, ah1, ah2, ah3, bl0[ni], bl1[ni]);
                    #pragma unroll
                    for (int ni = 0; ni < 4; ni++)
                        MMA_TF32(acc[mi][ni], al0, al1, al2, al3, bh0[ni], bh1[ni]);
                }
            }
        }
        __syncthreads();   // single barrier per k-tile
    }

    // Epilogue: accs -> smem -> coalesced gmem
    float* Cst = smem;
    #pragma unroll
    for (int mi = 0; mi < 4; mi++) {
        int row = wm * 64 + mi * 16 + gq;
        #pragma unroll
        for (int ni = 0; ni < 4; ni++) {
            int col = wn * 32 + ni * 8 + gr * 2;
            Cst[row * 132 + col]           = acc[mi][ni][0];
            Cst[row * 132 + col + 1]       = acc[mi][ni][1];
            Cst[(row + 8) * 132 + col]     = acc[mi][ni][2];
            Cst[(row + 8) * 132 + col + 1] = acc[mi][ni][3];
        }
    }
    __syncthreads();

    for (int idx = tid; idx < BM * BN / 4; idx += 512) {
        int r2 = idx >> 5, c4 = (idx & 31) << 2;
        float4 v = *(float4*)&Cst[r2 * 132 + c4];
        v.x *= alpha; v.y *= alpha; v.z *= alpha; v.w *= alpha;
        if (bias) {
            float4 bb = *(const float4*)&bias[bn + c4];
            v.x += bb.x; v.y += bb.y; v.z += bb.z; v.w += bb.w;
        }
        if (relu) {
            v.x = fmaxf(v.x, 0.f); v.y = fmaxf(v.y, 0.f);
            v.z = fmaxf(v.z, 0.f); v.w = fmaxf(v.w, 0.f);
        }
        *(float4*)&C[(long long)(bm + r2) * ldc + bn + c4] = v;
    }
}

// ---------------------------------------------------------------------------
// V transpose: vt[bh][n][k] = qkv[b][k][2E + h*HD + n]
// ---------------------------------------------------------------------------
__global__ void transpose_v(const float* __restrict__ qkv, float* __restrict__ vt)
{
    __shared__ float t[32][33];
    int z = blockIdx.z, zb = z >> 1, zh = z & 1;
    const float* src = qkv + (long long)zb * Sq * 3 * Eq + 2 * Eq + zh * HDq;
    float* dst = vt + (long long)z * HDq * Sq;
    int k0 = blockIdx.x * 32, n0 = blockIdx.y * 32;
    int tx = threadIdx.x, ty = threadIdx.y;
    #pragma unroll
    for (int j = 0; j < 4; j++)
        t[ty + j * 8][tx] = src[(long long)(k0 + ty + j * 8) * (3 * Eq) + n0 + tx];
    __syncthreads();
    #pragma unroll
    for (int j = 0; j < 4; j++)
        dst[(long long)(n0 + ty + j * 8) * Sq + k0 + tx] = t[tx][ty + j * 8];
}

// ---------------------------------------------------------------------------
// Row softmax over 512 columns. One warp per row.
// ---------------------------------------------------------------------------
__global__ __launch_bounds__(256) void softmax_rows(float* __restrict__ S)
{
    int row  = blockIdx.x * 8 + (threadIdx.x >> 5);
    int lane = threadIdx.x & 31;
    float* p = S + (long long)row * 512;

    float v[16];
    float m = -1e30f;
    #pragma unroll
    for (int i = 0; i < 16; i++) { v[i] = p[lane + i * 32]; m = fmaxf(m, v[i]); }
    #pragma unroll
    for (int o = 16; o > 0; o >>= 1) m = fmaxf(m, __shfl_xor_sync(0xffffffffu, m, o));
    float s = 0.f;
    #pragma unroll
    for (int i = 0; i < 16; i++) { v[i] = __expf(v[i] - m); s += v[i]; }
    #pragma unroll
    for (int o = 16; o > 0; o >>= 1) s += __shfl_xor_sync(0xffffffffu, s, o);
    float inv = 1.0f / s;
    #pragma unroll
    for (int i = 0; i < 16; i++) p[lane + i * 32] = v[i] * inv;
}

// ---------------------------------------------------------------------------
// Pack crf_w/ent_w (+biases)
// ---------------------------------------------------------------------------
__global__ void prep_wpad(const float* __restrict__ crf_w, const float* __restrict__ crf_b,
                          const float* __restrict__ ent_w, const float* __restrict__ ent_b,
                          float* __restrict__ Wp, float* __restrict__ bp)
{
    int i = blockIdx.x * blockDim.x + threadIdx.x;
    int r = i >> 9, c = i & 511;
    float v = 0.f;
    if (r < 24)      v = crf_w[r * 512 + c];
    else if (r < 26) v = ent_w[(r - 24) * 512 + c];
    Wp[i] = v;
    if (c == 0) {
        float b = 0.f;
        if (r < 24)      b = crf_b[r];
        else if (r < 26) b = ent_b[r - 24];
        bp[r] = b;
    }
}

// ---------------------------------------------------------------------------
// Emissions + entity log-softmax. One warp per row; coalesced k-interleaved
// weight loads + butterfly reduction.
// ---------------------------------------------------------------------------
__global__ void em_seg(const float* __restrict__ dec,
                       const float* __restrict__ Wp, const float* __restrict__ bp,
                       float* __restrict__ em, float* __restrict__ seg_out)
{
    int lane = threadIdx.x;
    int m    = blockIdx.x * blockDim.y + threadIdx.y;
    const float4* d4 = (const float4*)(dec + (long long)m * 512);

    float4 d[4];
    #pragma unroll
    for (int i = 0; i < 4; i++) d[i] = d4[i * 32 + lane];

    float s24 = 0.f, s25 = 0.f;
    #pragma unroll
    for (int t = 0; t < 26; t++) {
        const float4* w4 = (const float4*)(Wp + t * 512);
        float acc = 0.f;
        #pragma unroll
        for (int i = 0; i < 4; i++) {
            float4 w = w4[i * 32 + lane];
            acc = fmaf(d[i].x, w.x, acc);
            acc = fmaf(d[i].y, w.y, acc);
            acc = fmaf(d[i].z, w.z, acc);
            acc = fmaf(d[i].w, w.w, acc);
        }
        #pragma unroll
        for (int o = 16; o > 0; o >>= 1) acc += __shfl_xor_sync(0xffffffffu, acc, o);
        acc += bp[t];
        if (t < 24) {
            if (lane == t) em[(long long)m * 24 + t] = acc;
        } else if (t == 24) s24 = acc;
        else s25 = acc;
    }
    if (lane == 0) {
        float mx  = fmaxf(s24, s25);
        float lse = mx + __logf(__expf(s24 - mx) + __expf(s25 - mx));
        seg_out[(long long)m * 2 + 0] = s24 - lse;
        seg_out[(long long)m * 2 + 1] = s25 - lse;
    }
}

// ---------------------------------------------------------------------------
// CRF numerator
// ---------------------------------------------------------------------------
__global__ void crf_num_k(const float* __restrict__ em, const int* __restrict__ labels,
                          const float* __restrict__ start_t, const float* __restrict__ end_t,
                          const float* __restrict__ trans, float* __restrict__ num)
{
    int b = blockIdx.x, tid = threadIdx.x;
    __shared__ float red[256];
    const int* lb = labels + b * 512;
    const float* emb = em + (long long)b * 512 * 24;

    float s = 0.f;
    for (int t = 1 + tid; t < 512; t += 256) {
        int prev = lb[t - 1], cur = lb[t];
        s += trans[prev * 24 + cur] + emb[t * 24 + cur];
    }
    if (tid == 0)
        s += start_t[lb[0]] + emb[lb[0]] + end_t[lb[511]];

    red[tid] = s;
    __syncthreads();
    for (int o = 128; o > 0; o >>= 1) {
        if (tid < o) red[tid] += red[tid + o];
        __syncthreads();
    }
    if (tid == 0) num[b] = red[0];
}

// ---------------------------------------------------------------------------
// Fused CRF scans: blocks 0..31 -> normalizer; blocks 32..63 -> viterbi
// ---------------------------------------------------------------------------
__global__ void crf_scan_k(const float* __restrict__ em,
                           const float* __restrict__ start_t, const float* __restrict__ end_t,
                           const float* __restrict__ trans,
                           float* __restrict__ den, float* __restrict__ out_crf)
{
    int lane = threadIdx.x;
    __shared__ float al[2][32];
    __shared__ unsigned char hist[511][24];

    if (blockIdx.x < 32) {
        int b = blockIdx.x;
        const float* emb = em + (long long)b * 512 * 24;
        float trc[24];
        if (lane < 24) {
            #pragma unroll
            for (int t = 0; t < 24; t++) trc[t] = trans[t * 24 + lane];
            al[0][lane] = start_t[lane] + emb[lane];
        }
        __syncwarp();
        int cur = 0;
        for (int s = 1; s < 512; s++) {
            float nv = 0.f;
            if (lane < 24) {
                float v[24];
                float mx = -1e30f;
                #pragma unroll
                for (int t = 0; t < 24; t++) { v[t] = al[cur][t] + trc[t]; mx = fmaxf(mx, v[t]); }
                float sum = 0.f;
                #pragma unroll
                for (int t = 0; t < 24; t++) sum += __expf(v[t] - mx);
                nv = mx + __logf(sum) + emb[s * 24 + lane];
            }
            al[cur ^ 1][lane] = nv;
            __syncwarp();
            cur ^= 1;
        }
        if (lane == 0) {
            float mx = -1e30f;
            for (int t = 0; t < 24; t++) mx = fmaxf(mx, al[cur][t] + end_t[t]);
            float sum = 0.f;
            for (int t = 0; t < 24; t++) sum += __expf(al[cur][t] + end_t[t] - mx);
            den[b] = mx + __logf(sum);
        }
    } else {
        int b = blockIdx.x - 32;
        const float* emb = em + (long long)b * 512 * 24;
        float trc[24];
        if (lane < 24) {
            #pragma unroll
            for (int t = 0; t < 24; t++) trc[t] = trans[t * 24 + lane];
            al[0][lane] = start_t[lane] + emb[lane];
        }
        __syncwarp();
        int cur = 0;
        for (int s = 1; s < 512; s++) {
            float nv = 0.f;
            if (lane < 24) {
                float best = -1e30f;
                int bi = 0;
                #pragma unroll
                for (int t = 0; t < 24; t++) {
                    float v = al[cur][t] + trc[t];
                    if (v > best) { best = v; bi = t; }
                }
                nv = best + emb[s * 24 + lane];
                hist[s - 1][lane] = (unsigned char)bi;
            }
            al[cur ^ 1][lane] = nv;
            __syncwarp();
            cur ^= 1;
        }
        if (lane == 0) {
            float best = -1e30f;
            int last = 0;
            for (int t = 0; t < 24; t++) {
                float v = al[cur][t] + end_t[t];
                if (v > best) { best = v; last = t; }
            }
            float* po = out_crf + b * 512;
            po[511] = (float)last;
            int tag = last;
            for (int i = 510; i >= 0; i--) {
                tag = hist[i][tag];
                po[i] = (float)tag;
            }
        }
    }
}

// ---------------------------------------------------------------------------
// Loss
// ---------------------------------------------------------------------------
__global__ void loss_k(const float* __restrict__ num, const float* __restrict__ den,
                       float* __restrict__ out)
{
    int lane = threadIdx.x;
    float v = num[lane] - den[lane];
    #pragma unroll
    for (int o = 16; o > 0; o >>= 1) v += __shfl_xor_sync(0xffffffffu, v, o);
    if (lane == 0) out[0] = -v / 16384.0f;
}

// ---------------------------------------------------------------------------
// Launch
// ---------------------------------------------------------------------------
extern "C" void kernel_launch(void* const* d_in, const int* in_sizes, int n_in,
                              void* d_out, int out_size)
{
    const float* enc     = (const float*)d_in[0];
    const int*   labels  = (const int*)  d_in[1];
    const float* Win     = (const float*)d_in[3];
    const float* bin_    = (const float*)d_in[4];
    const float* Wout    = (const float*)d_in[5];
    const float* bout    = (const float*)d_in[6];
    const float* crf_w   = (const float*)d_in[7];
    const float* crf_b   = (const float*)d_in[8];
    const float* start_t = (const float*)d_in[9];
    const float* end_t   = (const float*)d_in[10];
    const float* trans   = (const float*)d_in[11];
    const float* ent_w   = (const float*)d_in[12];
    const float* ent_b   = (const float*)d_in[13];
    float* out = (float*)d_out;

    float *qkv, *vt, *scores, *attn, *dec, *em, *wpad, *bpad, *num, *den;
    cudaGetSymbolAddress((void**)&qkv,    g_qkv);
    cudaGetSymbolAddress((void**)&vt,     g_vt);
    cudaGetSymbolAddress((void**)&scores, g_scores);
    cudaGetSymbolAddress((void**)&attn,   g_attn);
    cudaGetSymbolAddress((void**)&dec,    g_dec);
    cudaGetSymbolAddress((void**)&em,     g_em);
    cudaGetSymbolAddress((void**)&wpad,   g_wpad);
    cudaGetSymbolAddress((void**)&bpad,   g_bpad);
    cudaGetSymbolAddress((void**)&num,    g_num);
    cudaGetSymbolAddress((void**)&den,    g_den);

    cudaFuncSetAttribute(gemm_mma, cudaFuncAttributeMaxDynamicSharedMemorySize, GEMM_SMEM);

    prep_wpad<<<64, 256>>>(crf_w, crf_b, ent_w, ent_b, wpad, bpad);

    // 1) QKV = enc @ Win^T + bin_   (16384 x 1536, K=512)
    gemm_mma<<<dim3(12, 64, 1), 512, GEMM_SMEM>>>(
        enc, Eq, 0, 0,
        Win, Eq, 0, 0,
        bin_,
        qkv, 3 * Eq, 0, 0,
        Eq, 1.0f, 0, 1);

    // 1b) V transpose for NT attnV
    transpose_v<<<dim3(16, 8, Bq * Hq), dim3(32, 8)>>>(qkv, vt);

    // 2) scores = Q @ K^T / 16   (per bh: 512x512, K=256)
    gemm_mma<<<dim3(4, 2, Bq * Hq), 512, GEMM_SMEM>>>(
        qkv,      3 * Eq, (long long)Sq * 3 * Eq, HDq,
        qkv + Eq, 3 * Eq, (long long)Sq * 3 * Eq, HDq,
        nullptr,
        scores, Sq, (long long)Hq * Sq * Sq, (long long)Sq * Sq,
        HDq, 0.0625f, 0, Hq);

    // 3) softmax
    softmax_rows<<<(Bq * Hq * Sq) / 8, 256>>>(scores);

    // 4) attn = P @ V   (per bh: 512x256, K=512) via NT with vt
    gemm_mma<<<dim3(2, 2, Bq * Hq), 512, GEMM_SMEM>>>(
        scores, Sq, (long long)Hq * Sq * Sq, (long long)Sq * Sq,
        vt,     Sq, (long long)Hq * HDq * Sq, (long long)HDq * Sq,
        nullptr,
        attn, Eq, (long long)Sq * Eq, HDq,
        Sq, 1.0f, 0, Hq);

    // 5) dec = relu(attn @ Wout^T + bout)
    gemm_mma<<<dim3(4, 64, 1), 512, GEMM_SMEM>>>(
        attn, Eq, 0, 0,
        Wout, Eq, 0, 0,
        bout,
        dec, Eq, 0, 0,
        Eq, 1.0f, 1, 1);

    // 6) emissions + entity log-softmax
    em_seg<<<Mq / 8, dim3(32, 8)>>>(dec, wpad, bpad, em, out + Mq);

    // 7) CRF
    crf_num_k<<<Bq, 256>>>(em, labels, start_t, end_t, trans, num);
    crf_scan_k<<<2 * Bq, 32>>>(em, start_t, end_t, trans, den, out);

    // 8) loss
    loss_k<<<1, 32>>>(num, den, out + Mq + 2 * Mq);
}